// round 1
// baseline (speedup 1.0000x reference)
#include <cuda_runtime.h>
#include <math.h>

#define BB 16
#define NN 8400
#define GG 128
#define NCL 5
#define BN (BB*NN)      // 134400
#define BGT (BB*GG)     // 2048
#define NPT 33          // ceil(8400/256)
#define MAXTK 18        // TOPK + TINY_BOOST + 1
#define EPSF 1e-9f
#define HPI_F 1.57079632679489662f
#define PI_F  3.14159265358979323f
#define IPI_F 0.318309886183790672f

struct GTC {
    float gx, gy, ct, st;
    float w15, h15, inv_s2, inv_sc2;
    float factor, gth;
    int budget, fbk, flags, lbl;
    float pad0, pad1;
};

__device__ GTC            d_gt[BGT];
__device__ float          d_lcls[BB * NCL * NN];   // [b][c][n] : ALPHA*log(sigmoid+EPS)
__device__ float4         d_pb[BN];                // (px, py, theta, 0)
__device__ float          d_am[(size_t)BGT * NN];  // [b][g][n] masked align
__device__ int            d_norm[BN];              // float-as-int atomicMax target
__device__ unsigned char  d_pos[BN];

// ---------------------------------------------------------------------------
// Pass 0a: per-anchor precompute + scratch init
// ---------------------------------------------------------------------------
__global__ __launch_bounds__(256) void prep_anchor(const float* __restrict__ ps,
                                                   const float* __restrict__ pbx) {
    int idx = blockIdx.x * 256 + threadIdx.x;
    if (idx >= BN) return;
    int b = idx / NN;
    int n = idx - b * NN;
    const float* s = ps + (size_t)idx * NCL;
#pragma unroll
    for (int c = 0; c < NCL; c++) {
        float sg = 1.f / (1.f + expf(-s[c]));
        sg = fminf(fmaxf(sg, EPSF), 1.f);
        d_lcls[(b * NCL + c) * NN + n] = 0.5f * logf(sg + EPSF);
    }
    const float* pp = pbx + (size_t)idx * 5;
    d_pb[idx] = make_float4(pp[0], pp[1], pp[4], 0.f);
    d_norm[idx] = 0;
    d_pos[idx] = 0;
}

// ---------------------------------------------------------------------------
// Pass 0b: per-GT constants
// ---------------------------------------------------------------------------
__global__ __launch_bounds__(256) void prep_gt(const int* __restrict__ gl,
                                               const float* __restrict__ gb,
                                               const float* __restrict__ mg) {
    int bg = blockIdx.x * 256 + threadIdx.x;
    if (bg >= BGT) return;
    const float* g = gb + (size_t)bg * 5;
    float gx = g[0], gy = g[1], w = g[2], h = g[3], th = g[4];
    float wc = fmaxf(w, EPSF), hc = fmaxf(h, EPSF);
    float area = wc * hc;
    float ar = fmaxf(wc / hc, hc / wc);
    float sev = fminf(fmaxf((0.01f - area) / (0.01f + EPSF), 0.f), 1.f);
    int te = (int)ceilf(sev * 4.f);
    int el = (ar >= 4.f) ? 1 : 0;
    GTC q;
    q.gx = gx; q.gy = gy;
    q.ct = cosf(-th); q.st = sinf(-th);
    q.w15 = w * 1.5f; q.h15 = h * 1.5f;
    float sc = sqrtf(w * h);
    float is = 1.f / (sc + 1e-6f);        q.inv_s2  = is * is;
    float isc = 1.f / (sc * 1.5f + 1e-6f); q.inv_sc2 = isc * isc;
    float strength = fminf(fmaxf((ar - 4.f) / (4.f + EPSF), 0.f), 1.f);
    q.factor = (1.f + sev * (4.f / 13.f)) * (1.f + 0.25f * strength);
    q.gth = th;
    q.budget = 13 + te + el;       // in [13,18], clip to [1,N] is vacuous
    q.fbk = te + el + 3;           // max(budget-13+3, 3)
    int fl = (mg[bg] > 0.f) ? 1 : 0;
    if ((area < 0.01f) || (ar >= 4.f)) fl |= 2;
    q.flags = fl;
    q.lbl = gl[bg];
    q.pad0 = 0.f; q.pad1 = 0.f;
    d_gt[bg] = q;
}

// ---------------------------------------------------------------------------
// Pass B: one block per (b,g). in-centers + fallback + align + top-18 + scatter
// ---------------------------------------------------------------------------
__global__ __launch_bounds__(256) void main_kernel(const float2* __restrict__ anch) {
    int bg = blockIdx.x;
    int b = bg >> 7;
    int tid = threadIdx.x;
    int lane = tid & 31, wid = tid >> 5;

    GTC q = d_gt[bg];
    float* amrow = d_am + (size_t)bg * NN;

    if (!(q.flags & 1)) {  // mask_gt == 0 -> am row all zero, nothing else
        for (int n = tid; n < NN; n += 256) amrow[n] = 0.f;
        return;
    }

    __shared__ unsigned long long s_red[8];
    __shared__ int                s_ired[8];
    __shared__ unsigned long long s_best;
    __shared__ unsigned long long s_topk[MAXTK];
    __shared__ int                s_cnt;
    __shared__ unsigned int       s_chosen[8];

    // -------- pass 1: rotated in-center test + count --------
    unsigned long long lb = 0ull;
    int cnt = 0;
#pragma unroll
    for (int sl = 0; sl < NPT; sl++) {
        int n = sl * 256 + tid;
        if (n < NN) {
            float2 a = anch[n];
            float dx = a.x - q.gx, dy = a.y - q.gy;
            float lx = dx * q.ct - dy * q.st;
            float ly = dx * q.st + dy * q.ct;
            if (fabsf(lx) < q.w15 && fabsf(ly) < q.h15) { lb |= (1ull << sl); cnt++; }
        }
    }
#pragma unroll
    for (int o = 16; o; o >>= 1) cnt += __shfl_xor_sync(0xffffffffu, cnt, o);
    if (lane == 0) s_ired[wid] = cnt;
    __syncthreads();
    if (tid == 0) {
        int t = 0;
        for (int i = 0; i < 8; i++) t += s_ired[i];
        s_cnt = t;
    }
    __syncthreads();
    int total = s_cnt;

    // -------- tiny/elongated fallback: 8 nearest anchors (rare path) --------
    if (total == 0 && (q.flags & 2)) {
        for (int r = 0; r < 8; r++) {
            unsigned long long key = 0xFFFFFFFFFFFFFFFFull;
#pragma unroll
            for (int sl = 0; sl < NPT; sl++) {
                int n = sl * 256 + tid;
                if (n < NN) {
                    bool skip = false;
                    for (int qq = 0; qq < r; qq++)
                        if (s_chosen[qq] == (unsigned)n) skip = true;
                    if (!skip) {
                        float2 a = anch[n];
                        float dx = a.x - q.gx, dy = a.y - q.gy;
                        float d2 = dx * dx + dy * dy;
                        unsigned long long k =
                            ((unsigned long long)__float_as_uint(d2) << 32) | (unsigned)n;
                        if (k < key) key = k;
                    }
                }
            }
#pragma unroll
            for (int o = 16; o; o >>= 1) {
                unsigned long long t = __shfl_xor_sync(0xffffffffu, key, o);
                if (t < key) key = t;
            }
            if (lane == 0) s_red[wid] = key;
            __syncthreads();
            if (wid == 0) {
                unsigned long long v = (lane < 8) ? s_red[lane] : 0xFFFFFFFFFFFFFFFFull;
#pragma unroll
                for (int o = 4; o; o >>= 1) {
                    unsigned long long t = __shfl_xor_sync(0xffffffffu, v, o);
                    if (t < v) v = t;
                }
                if (lane == 0) s_chosen[r] = (unsigned)(v & 0xffffffffu);
            }
            __syncthreads();
            unsigned nwin = s_chosen[r];
            if (r < q.fbk && (int)(nwin & 255u) == tid) lb |= (1ull << (nwin >> 8));
            __syncthreads();
        }
    }

    // -------- pass 2: align metric (masked by in-centers), cached in regs --------
    float av[NPT];
    const float*  lcl = d_lcls + ((size_t)b * NCL + q.lbl) * NN;
    const float4* pbb = d_pb + (size_t)b * NN;
#pragma unroll
    for (int sl = 0; sl < NPT; sl++) {
        int n = sl * 256 + tid;
        float a = 0.f;
        if (n < NN && ((lb >> sl) & 1ull)) {
            float4 p = pbb[n];
            float dx = p.x - q.gx, dy = p.y - q.gy;
            float t = (dx * dx + dy * dy) * q.inv_s2;
            float ov = expf(-t);
            float lov = logf(ov + EPSF);
            float2 an = anch[n];
            float ax = an.x - q.gx, ay = an.y - q.gy;
            float c = (ax * ax + ay * ay) * q.inv_sc2;
            float wv = (p.z - q.gth) + HPI_F;
            wv = wv - PI_F * floorf(wv * IPI_F);
            float wr = wv - HPI_F;
            float e = lcl[n];
            float al = expf(e + 6.f * lov - 1.5f * fabsf(wr) - c) * q.factor;
            a = fmaxf(al, 0.f);   // cleans NaN and negatives (matches nan_to_num+max)
        }
        av[sl] = a;
        if (n < NN) amrow[n] = a;
    }

    // -------- top-18 extraction: per-thread reg cache, winner-only rescan --------
    unsigned long long rm = 0ull;
    if (tid >= 208) rm = (1ull << 32);   // slot 32 invalid for tid>=208 (n>=8400)
    unsigned long long cur = 0ull;
#pragma unroll
    for (int sl = 0; sl < NPT; sl++) {
        if (!((rm >> sl) & 1ull)) {
            unsigned n = (unsigned)(sl * 256 + tid);
            unsigned long long k =
                ((unsigned long long)__float_as_uint(av[sl]) << 32) | (16384u - n);
            if (k > cur) cur = k;
        }
    }
    for (int r = 0; r < MAXTK; r++) {
        unsigned long long k = cur;
#pragma unroll
        for (int o = 16; o; o >>= 1) {
            unsigned long long t = __shfl_xor_sync(0xffffffffu, k, o);
            if (t > k) k = t;
        }
        if (lane == 0) s_red[wid] = k;
        __syncthreads();
        if (wid == 0) {
            unsigned long long v = (lane < 8) ? s_red[lane] : 0ull;
#pragma unroll
            for (int o = 4; o; o >>= 1) {
                unsigned long long t = __shfl_xor_sync(0xffffffffu, v, o);
                if (t > v) v = t;
            }
            if (lane == 0) { s_best = v; s_topk[r] = v; }
        }
        __syncthreads();
        unsigned nwin = 16384u - (unsigned)(s_best & 0xffffffffu);
        if ((int)(nwin & 255u) == tid) {
            rm |= (1ull << (nwin >> 8));
            unsigned long long c2 = 0ull;
#pragma unroll
            for (int sl = 0; sl < NPT; sl++) {
                if (!((rm >> sl) & 1ull)) {
                    unsigned n2 = (unsigned)(sl * 256 + tid);
                    unsigned long long kk =
                        ((unsigned long long)__float_as_uint(av[sl]) << 32) | (16384u - n2);
                    if (kk > c2) c2 = kk;
                }
            }
            cur = c2;
        }
        __syncthreads();
    }

    // -------- epilogue (one warp): dyn_k, selection, norm scatter --------
    if (wid == 0) {
        int j = lane;
        float val = 0.f; unsigned nj = 0; float ovj = 0.f;
        if (j < MAXTK) {
            unsigned long long k = s_topk[j];
            val = __uint_as_float((unsigned)(k >> 32));
            nj = 16384u - (unsigned)(k & 0xffffffffu);
            float4 p = pbb[nj];
            float dx = p.x - q.gx, dy = p.y - q.gy;
            float t = (dx * dx + dy * dy) * q.inv_s2;
            float ov = expf(-t);
            ovj = fminf(fmaxf(ov, 0.f), 1.f);  // fmaxf cleans NaN
        }
        float s = ovj;
#pragma unroll
        for (int o = 16; o; o >>= 1) s += __shfl_xor_sync(0xffffffffu, s, o);
        float dk = rintf(s);                  // round-half-even == jnp.round
        dk = fmaxf(dk, 1.f);
        dk = fminf(dk, (float)q.budget);
        int dyn = (int)dk;
        bool sel = (j < MAXTK) && (val > EPSF) && (j < dyn);
        unsigned bal = __ballot_sync(0xffffffffu, sel);
        if (bal) {
            int first = __ffs(bal) - 1;
            float maxalign = __shfl_sync(0xffffffffu, val, first);  // largest selected
            float mo = sel ? ovj : 0.f;
#pragma unroll
            for (int o = 16; o; o >>= 1) mo = fmaxf(mo, __shfl_xor_sync(0xffffffffu, mo, o));
            if (sel) {
                float nv = val * mo / (maxalign + EPSF);
                atomicMax(d_norm + b * NN + nj, __float_as_int(nv));
                d_pos[b * NN + nj] = 1;
            }
        }
    }
}

// ---------------------------------------------------------------------------
// Pass C: per-anchor argmax over g + all outputs
//   out = [labels BN | bboxes BN*5 | scores BN*5 | pos BN]  (float32)
// ---------------------------------------------------------------------------
__global__ __launch_bounds__(256) void out_kernel(const int* __restrict__ gl,
                                                  const float* __restrict__ gb,
                                                  float* __restrict__ out) {
    int n = blockIdx.x * 256 + threadIdx.x;
    int b = blockIdx.y;
    if (n >= NN) return;
    const float* amp = d_am + (size_t)b * GG * NN + n;
    float best = amp[0];
    int bg2 = 0;
#pragma unroll 8
    for (int g = 1; g < GG; g++) {
        float v = amp[(size_t)g * NN];
        if (v > best) { best = v; bg2 = g; }   // strict > keeps first max (jnp.argmax)
    }
    int idx = b * NN + n;
    bool pos = d_pos[idx] != 0;
    int lab = gl[b * GG + bg2];
    out[idx] = pos ? (float)lab : 5.f;
    const float* gp = gb + (size_t)(b * GG + bg2) * 5;
    float* ob = out + BN + (size_t)idx * 5;
    ob[0] = gp[0]; ob[1] = gp[1]; ob[2] = gp[2]; ob[3] = gp[3]; ob[4] = gp[4];
    float nv = __int_as_float(d_norm[idx]);
    float* os = out + (size_t)BN * 6 + (size_t)idx * 5;
#pragma unroll
    for (int c2 = 0; c2 < 5; c2++) os[c2] = (pos && c2 == lab) ? nv : 0.f;
    out[(size_t)BN * 11 + idx] = pos ? 1.f : 0.f;
}

// ---------------------------------------------------------------------------
extern "C" void kernel_launch(void* const* d_in, const int* in_sizes, int n_in,
                              void* d_out, int out_size) {
    const float* ps  = (const float*)d_in[0];   // pred_scores   (B,N,5)
    const float* pbx = (const float*)d_in[1];   // pred_bboxes   (B,N,5)
    const float* ap  = (const float*)d_in[2];   // anchor_points (N,2)
    const int*   gl  = (const int*)d_in[3];     // gt_labels     (B,G,1)
    const float* gbx = (const float*)d_in[4];   // gt_bboxes     (B,G,5)
    const float* mg  = (const float*)d_in[5];   // mask_gt       (B,G,1)

    prep_anchor<<<(BN + 255) / 256, 256>>>(ps, pbx);
    prep_gt<<<(BGT + 255) / 256, 256>>>(gl, gbx, mg);
    main_kernel<<<BGT, 256>>>((const float2*)ap);
    dim3 og((NN + 255) / 256, BB);
    out_kernel<<<og, 256>>>(gl, gbx, (float*)d_out);
}

// round 2
// speedup vs baseline: 1.0947x; 1.0947x over previous
#include <cuda_runtime.h>
#include <math.h>

#define BB 16
#define NN 8400
#define GG 128
#define NCL 5
#define BN (BB*NN)      // 134400
#define BGT (BB*GG)     // 2048
#define NPT 33          // ceil(8400/256)
#define MAXTK 18        // TOPK + TINY_BOOST + 1
#define EPSF 1e-9f
#define HPI_F 1.57079632679489662f
#define PI_F  3.14159265358979323f
#define IPI_F 0.318309886183790672f

struct GTC {
    float gx, gy, ct, st;
    float w15, h15, inv_s2, inv_sc2;
    float factor, gth;
    int budget, fbk, flags, lbl;
    float pad0, pad1;
};

__device__ GTC            d_gt[BGT];
__device__ float          d_lcls[BB * NCL * NN];   // [b][c][n] : 0.5*log(sigmoid+EPS)
__device__ float4         d_pb[BN];                // (px, py, theta, 0)
__device__ float          d_am[(size_t)BGT * NN];  // [b][g][n] masked align
__device__ int            d_norm[BN];
__device__ unsigned char  d_pos[BN];

// ---------------------------------------------------------------------------
__global__ __launch_bounds__(256) void prep_anchor(const float* __restrict__ ps,
                                                   const float* __restrict__ pbx) {
    int idx = blockIdx.x * 256 + threadIdx.x;
    if (idx >= BN) return;
    int b = idx / NN;
    int n = idx - b * NN;
    const float* s = ps + (size_t)idx * NCL;
#pragma unroll
    for (int c = 0; c < NCL; c++) {
        float sg = 1.f / (1.f + expf(-s[c]));
        sg = fminf(fmaxf(sg, EPSF), 1.f);
        d_lcls[(b * NCL + c) * NN + n] = 0.5f * logf(sg + EPSF);
    }
    const float* pp = pbx + (size_t)idx * 5;
    d_pb[idx] = make_float4(pp[0], pp[1], pp[4], 0.f);
    d_norm[idx] = 0;
    d_pos[idx] = 0;
}

// ---------------------------------------------------------------------------
__global__ __launch_bounds__(256) void prep_gt(const int* __restrict__ gl,
                                               const float* __restrict__ gb,
                                               const float* __restrict__ mg) {
    int bg = blockIdx.x * 256 + threadIdx.x;
    if (bg >= BGT) return;
    const float* g = gb + (size_t)bg * 5;
    float gx = g[0], gy = g[1], w = g[2], h = g[3], th = g[4];
    float wc = fmaxf(w, EPSF), hc = fmaxf(h, EPSF);
    float area = wc * hc;
    float ar = fmaxf(wc / hc, hc / wc);
    float sev = fminf(fmaxf((0.01f - area) / (0.01f + EPSF), 0.f), 1.f);
    int te = (int)ceilf(sev * 4.f);
    int el = (ar >= 4.f) ? 1 : 0;
    GTC q;
    q.gx = gx; q.gy = gy;
    q.ct = cosf(-th); q.st = sinf(-th);
    q.w15 = w * 1.5f; q.h15 = h * 1.5f;
    float sc = sqrtf(w * h);
    float is = 1.f / (sc + 1e-6f);         q.inv_s2  = is * is;
    float isc = 1.f / (sc * 1.5f + 1e-6f); q.inv_sc2 = isc * isc;
    float strength = fminf(fmaxf((ar - 4.f) / (4.f + EPSF), 0.f), 1.f);
    q.factor = (1.f + sev * (4.f / 13.f)) * (1.f + 0.25f * strength);
    q.gth = th;
    q.budget = 13 + te + el;
    q.fbk = te + el + 3;
    int fl = (mg[bg] > 0.f) ? 1 : 0;
    if ((area < 0.01f) || (ar >= 4.f)) fl |= 2;
    q.flags = fl;
    q.lbl = gl[bg];
    q.pad0 = 0.f; q.pad1 = 0.f;
    d_gt[bg] = q;
}

// ---------------------------------------------------------------------------
// Main: one block per (b,g). Fused in-center + align (ballot skip), smem av,
// 18-round top-k with 1 barrier/round, warp-0 epilogue.
// ---------------------------------------------------------------------------
__global__ __launch_bounds__(256) void main_kernel(const float2* __restrict__ anch) {
    int bg = blockIdx.x;
    int b = bg >> 7;
    int tid = threadIdx.x;
    int lane = tid & 31, wid = tid >> 5;

    GTC q = d_gt[bg];
    float* amrow = d_am + (size_t)bg * NN;

    if (!(q.flags & 1)) {                 // mask_gt == 0
        float4* a4 = (float4*)amrow;
        for (int i = tid; i < NN / 4; i += 256) a4[i] = make_float4(0.f, 0.f, 0.f, 0.f);
        return;
    }

    __shared__ float              s_av[NN];          // 33.6 KB
    __shared__ unsigned long long s_red[2][8];
    __shared__ unsigned long long s_topk[MAXTK];
    __shared__ int                s_ired[8];
    __shared__ int                s_cnt;
    __shared__ unsigned int       s_chosen[8];

    const float*  lcl = d_lcls + ((size_t)b * NCL + q.lbl) * NN;
    const float4* pbb = d_pb + (size_t)b * NN;

    // -------- fused: in-center test + align, skip empty warp-slots --------
    int cnt = 0;
    for (int sl = 0; sl < NPT; sl++) {
        int n = sl * 256 + tid;
        bool in = false;
        float dx = 0.f, dy = 0.f;
        if (n < NN) {
            float2 a = anch[n];
            dx = a.x - q.gx; dy = a.y - q.gy;
            float lx = dx * q.ct - dy * q.st;
            float ly = dx * q.st + dy * q.ct;
            in = (fabsf(lx) < q.w15) && (fabsf(ly) < q.h15);
        }
        float v = 0.f;
        if (__ballot_sync(0xffffffffu, in)) {
            if (in) {
                cnt++;
                float4 p = pbb[n];
                float px = p.x - q.gx, py = p.y - q.gy;
                float t = (px * px + py * py) * q.inv_s2;
                float x = expf(-t) + EPSF;         // (ov + EPS)
                float x2 = x * x; float x6 = x2 * x2 * x2;
                float wv = (p.z - q.gth) + HPI_F;
                wv -= PI_F * floorf(wv * IPI_F);
                float wr = fabsf(wv - HPI_F);
                float c = (dx * dx + dy * dy) * q.inv_sc2;
                v = fmaxf(q.factor * x6 * expf(lcl[n] - 1.5f * wr - c), 0.f);
            }
        }
        if (n < NN) { s_av[n] = v; amrow[n] = v; }
    }
#pragma unroll
    for (int o = 16; o; o >>= 1) cnt += __shfl_xor_sync(0xffffffffu, cnt, o);
    if (lane == 0) s_ired[wid] = cnt;
    __syncthreads();
    if (tid == 0) {
        int t = 0;
        for (int i = 0; i < 8; i++) t += s_ired[i];
        s_cnt = t;
    }
    __syncthreads();

    // -------- tiny/elongated fallback (rare) --------
    if (s_cnt == 0 && (q.flags & 2)) {
        for (int r = 0; r < 8; r++) {
            unsigned long long key = 0xFFFFFFFFFFFFFFFFull;
            for (int sl = 0; sl < NPT; sl++) {
                int n = sl * 256 + tid;
                if (n < NN) {
                    bool skip = false;
                    for (int qq = 0; qq < r; qq++)
                        if (s_chosen[qq] == (unsigned)n) skip = true;
                    if (!skip) {
                        float2 a = anch[n];
                        float dx = a.x - q.gx, dy = a.y - q.gy;
                        float d2 = dx * dx + dy * dy;
                        unsigned long long k =
                            ((unsigned long long)__float_as_uint(d2) << 32) | (unsigned)n;
                        if (k < key) key = k;
                    }
                }
            }
#pragma unroll
            for (int o = 16; o; o >>= 1) {
                unsigned long long t = __shfl_xor_sync(0xffffffffu, key, o);
                if (t < key) key = t;
            }
            if (lane == 0) s_red[0][wid] = key;
            __syncthreads();
            if (wid == 0) {
                unsigned long long v = (lane < 8) ? s_red[0][lane] : 0xFFFFFFFFFFFFFFFFull;
#pragma unroll
                for (int o = 4; o; o >>= 1) {
                    unsigned long long t = __shfl_xor_sync(0xffffffffu, v, o);
                    if (t < v) v = t;
                }
                if (lane == 0) s_chosen[r] = (unsigned)(v & 0xffffffffu);
            }
            __syncthreads();
            unsigned nw = s_chosen[r];
            if (r < q.fbk && (int)(nw & 255u) == tid) {
                int n = (int)nw;
                float2 a = anch[n];
                float dx = a.x - q.gx, dy = a.y - q.gy;
                float4 p = pbb[n];
                float px = p.x - q.gx, py = p.y - q.gy;
                float t = (px * px + py * py) * q.inv_s2;
                float x = expf(-t) + EPSF;
                float x2 = x * x; float x6 = x2 * x2 * x2;
                float wv = (p.z - q.gth) + HPI_F;
                wv -= PI_F * floorf(wv * IPI_F);
                float wr = fabsf(wv - HPI_F);
                float c = (dx * dx + dy * dy) * q.inv_sc2;
                float v = fmaxf(q.factor * x6 * expf(lcl[n] - 1.5f * wr - c), 0.f);
                s_av[n] = v; amrow[n] = v;
            }
            __syncthreads();
        }
    }

    // -------- top-18: per-thread column max, winner-only rescan, 1 sync/round --------
    unsigned long long cur = 0ull, rm = 0ull;
    for (int sl = 0; sl < NPT; sl++) {
        int n = sl * 256 + tid;
        if (n < NN) {
            unsigned long long k =
                ((unsigned long long)__float_as_uint(s_av[n]) << 32) | (unsigned)(16384 - n);
            if (k > cur) cur = k;
        }
    }
    for (int r = 0; r < MAXTK; r++) {
        unsigned long long k = cur;
#pragma unroll
        for (int o = 16; o; o >>= 1) {
            unsigned long long t = __shfl_xor_sync(0xffffffffu, k, o);
            if (t > k) k = t;
        }
        if (lane == 0) s_red[r & 1][wid] = k;
        __syncthreads();
        unsigned long long best = s_red[r & 1][0];
#pragma unroll
        for (int i = 1; i < 8; i++) {
            unsigned long long t = s_red[r & 1][i];
            if (t > best) best = t;
        }
        if (tid == 0) s_topk[r] = best;
        unsigned nw = 16384u - (unsigned)(best & 0xffffffffu);
        if ((int)(nw & 255u) == tid) {
            rm |= (1ull << (nw >> 8));
            unsigned long long c2 = 0ull;
            for (int sl = 0; sl < NPT; sl++) {
                int n = sl * 256 + tid;
                if (n < NN && !((rm >> sl) & 1ull)) {
                    unsigned long long kk =
                        ((unsigned long long)__float_as_uint(s_av[n]) << 32) |
                        (unsigned)(16384 - n);
                    if (kk > c2) c2 = kk;
                }
            }
            cur = c2;
        }
    }
    __syncthreads();

    // -------- epilogue (warp 0): dyn_k, selection, norm scatter --------
    if (wid == 0) {
        int j = lane;
        float val = 0.f; unsigned nj = 0; float ovj = 0.f;
        if (j < MAXTK) {
            unsigned long long k = s_topk[j];
            val = __uint_as_float((unsigned)(k >> 32));
            nj = 16384u - (unsigned)(k & 0xffffffffu);
            float4 p = pbb[nj];
            float dx = p.x - q.gx, dy = p.y - q.gy;
            float t = (dx * dx + dy * dy) * q.inv_s2;
            float ov = expf(-t);
            ovj = fminf(fmaxf(ov, 0.f), 1.f);
        }
        float s = ovj;
#pragma unroll
        for (int o = 16; o; o >>= 1) s += __shfl_xor_sync(0xffffffffu, s, o);
        float dk = rintf(s);
        dk = fmaxf(dk, 1.f);
        dk = fminf(dk, (float)q.budget);
        int dyn = (int)dk;
        bool sel = (j < MAXTK) && (val > EPSF) && (j < dyn);
        unsigned bal = __ballot_sync(0xffffffffu, sel);
        if (bal) {
            int first = __ffs(bal) - 1;
            float maxalign = __shfl_sync(0xffffffffu, val, first);
            float mo = sel ? ovj : 0.f;
#pragma unroll
            for (int o = 16; o; o >>= 1) mo = fmaxf(mo, __shfl_xor_sync(0xffffffffu, mo, o));
            if (sel) {
                float nv = val * mo / (maxalign + EPSF);
                atomicMax(d_norm + b * NN + nj, __float_as_int(nv));
                d_pos[b * NN + nj] = 1;
            }
        }
    }
}

// ---------------------------------------------------------------------------
// Out: g-dim split across 8 warps, float4 loads, then per-anchor finish.
// ---------------------------------------------------------------------------
#define TN 128
__global__ __launch_bounds__(256) void out_kernel(const int* __restrict__ gl,
                                                  const float* __restrict__ gb,
                                                  float* __restrict__ out) {
    __shared__ unsigned long long s_k[8][TN];
    int b = blockIdx.y;
    int nbase = blockIdx.x * TN;
    int tid = threadIdx.x;
    int nt = tid & 31, gq = tid >> 5;
    int n4 = nbase + nt * 4;
    const float4* am4 = (const float4*)(d_am + (size_t)b * GG * NN);

    if (n4 < NN) {
        int g0 = gq * 16;
        float4 v = am4[((size_t)g0 * NN + n4) >> 2];
        float bv0 = v.x, bv1 = v.y, bv2 = v.z, bv3 = v.w;
        int bg0 = g0, bg1 = g0, bg2 = g0, bg3 = g0;
#pragma unroll
        for (int g = 1; g < 16; g++) {
            float4 w = am4[((size_t)(g0 + g) * NN + n4) >> 2];
            if (w.x > bv0) { bv0 = w.x; bg0 = g0 + g; }
            if (w.y > bv1) { bv1 = w.y; bg1 = g0 + g; }
            if (w.z > bv2) { bv2 = w.z; bg2 = g0 + g; }
            if (w.w > bv3) { bv3 = w.w; bg3 = g0 + g; }
        }
        int c0 = nt * 4;
        s_k[gq][c0 + 0] = ((unsigned long long)__float_as_uint(bv0) << 32) | (unsigned)(127 - bg0);
        s_k[gq][c0 + 1] = ((unsigned long long)__float_as_uint(bv1) << 32) | (unsigned)(127 - bg1);
        s_k[gq][c0 + 2] = ((unsigned long long)__float_as_uint(bv2) << 32) | (unsigned)(127 - bg2);
        s_k[gq][c0 + 3] = ((unsigned long long)__float_as_uint(bv3) << 32) | (unsigned)(127 - bg3);
    }
    __syncthreads();

    if (tid < TN) {
        int n = nbase + tid;
        if (n < NN) {
            unsigned long long best = s_k[0][tid];
#pragma unroll
            for (int w = 1; w < 8; w++) {
                unsigned long long t = s_k[w][tid];
                if (t > best) best = t;
            }
            int g = 127 - (int)(best & 0xffffffffu);
            int idx = b * NN + n;
            bool pos = d_pos[idx] != 0;
            int lab = gl[b * GG + g];
            out[idx] = pos ? (float)lab : 5.f;
            const float* gp = gb + (size_t)(b * GG + g) * 5;
            float* ob = out + BN + (size_t)idx * 5;
            ob[0] = gp[0]; ob[1] = gp[1]; ob[2] = gp[2]; ob[3] = gp[3]; ob[4] = gp[4];
            float nv = __int_as_float(d_norm[idx]);
            float* os = out + (size_t)BN * 6 + (size_t)idx * 5;
#pragma unroll
            for (int c = 0; c < 5; c++) os[c] = (pos && c == lab) ? nv : 0.f;
            out[(size_t)BN * 11 + idx] = pos ? 1.f : 0.f;
        }
    }
}

// ---------------------------------------------------------------------------
extern "C" void kernel_launch(void* const* d_in, const int* in_sizes, int n_in,
                              void* d_out, int out_size) {
    const float* ps  = (const float*)d_in[0];
    const float* pbx = (const float*)d_in[1];
    const float* ap  = (const float*)d_in[2];
    const int*   gl  = (const int*)d_in[3];
    const float* gbx = (const float*)d_in[4];
    const float* mg  = (const float*)d_in[5];

    prep_anchor<<<(BN + 255) / 256, 256>>>(ps, pbx);
    prep_gt<<<(BGT + 255) / 256, 256>>>(gl, gbx, mg);
    main_kernel<<<BGT, 256>>>((const float2*)ap);
    dim3 og((NN + TN - 1) / TN, BB);
    out_kernel<<<og, 256>>>(gl, gbx, (float*)d_out);
}

// round 3
// speedup vs baseline: 1.3554x; 1.2381x over previous
#include <cuda_runtime.h>
#include <math.h>

#define BB 16
#define NN 8400
#define GG 128
#define NCL 5
#define BN (BB*NN)      // 134400
#define BGT (BB*GG)     // 2048
#define NPT 33          // ceil(8400/256)
#define MAXTK 18        // TOPK + TINY_BOOST + 1
#define EPSF 1e-9f
#define HPI_F 1.57079632679489662f
#define PI_F  3.14159265358979323f
#define IPI_F 0.318309886183790672f

struct GTC {
    float gx, gy, ct, st;
    float w15, h15, inv_s2, inv_sc2;
    float factor, gth;
    int budget, fbk, flags, lbl;
    float pad0, pad1;
};

__device__ GTC                d_gt[BGT];
__device__ float              d_am[(size_t)BGT * NN];  // [b][g][n]
__device__ unsigned long long d_best[BN];              // (val<<32)|(127-g)
__device__ int                d_norm[BN];
__device__ unsigned char      d_pos[BN];
__device__ int                d_cnt[BGT];              // in-center counts

// ---------------------------------------------------------------------------
__global__ __launch_bounds__(256) void prep_gt(const int* __restrict__ gl,
                                               const float* __restrict__ gb,
                                               const float* __restrict__ mg) {
    int bg = blockIdx.x * 256 + threadIdx.x;
    if (bg >= BGT) return;
    const float* g = gb + (size_t)bg * 5;
    float gx = g[0], gy = g[1], w = g[2], h = g[3], th = g[4];
    float wc = fmaxf(w, EPSF), hc = fmaxf(h, EPSF);
    float area = wc * hc;
    float ar = fmaxf(wc / hc, hc / wc);
    float sev = fminf(fmaxf((0.01f - area) / (0.01f + EPSF), 0.f), 1.f);
    int te = (int)ceilf(sev * 4.f);
    int el = (ar >= 4.f) ? 1 : 0;
    GTC q;
    q.gx = gx; q.gy = gy;
    q.ct = cosf(-th); q.st = sinf(-th);
    q.w15 = w * 1.5f; q.h15 = h * 1.5f;
    float sc = sqrtf(w * h);
    float is = 1.f / (sc + 1e-6f);         q.inv_s2  = is * is;
    float isc = 1.f / (sc * 1.5f + 1e-6f); q.inv_sc2 = isc * isc;
    float strength = fminf(fmaxf((ar - 4.f) / (4.f + EPSF), 0.f), 1.f);
    q.factor = (1.f + sev * (4.f / 13.f)) * (1.f + 0.25f * strength);
    q.gth = th;
    q.budget = 13 + te + el;
    q.fbk = te + el + 3;
    int fl = (mg[bg] > 0.f) ? 1 : 0;
    if ((area < 0.01f) || (ar >= 4.f)) fl |= 2;
    q.flags = fl;
    q.lbl = gl[bg];
    q.pad0 = 0.f; q.pad1 = 0.f;
    d_gt[bg] = q;
    d_cnt[bg] = 0;
}

// ---------------------------------------------------------------------------
// A: block = (anchor tile of 256, b). Loop over all 128 GTs with GT data in
// smem and anchor/pred data in registers. Writes am rows, per-anchor argmax,
// per-(b,g) in-center counts.
// ---------------------------------------------------------------------------
__global__ __launch_bounds__(256) void pair_kernel(const float2* __restrict__ anch,
                                                   const float* __restrict__ ps,
                                                   const float* __restrict__ pbx) {
    int b   = blockIdx.y;
    int tid = threadIdx.x;
    int n   = blockIdx.x * 256 + tid;

    __shared__ GTC s_gt[GG];      // 8 KB
    __shared__ int s_cnt[GG];

    {   // stage 128 GT descriptors
        const float4* src = (const float4*)(d_gt + b * GG);
        float4*       dst = (float4*)s_gt;
        for (int i = tid; i < GG * 4; i += 256) dst[i] = src[i];
        if (tid < GG) s_cnt[tid] = 0;
    }
    __syncthreads();

    bool valid = (n < NN);
    float ax = 0.f, ay = 0.f, px = 0.f, py = 0.f, pth = 0.f;
    float l0 = 0.f, l1 = 0.f, l2 = 0.f, l3 = 0.f, l4 = 0.f;
    if (valid) {
        float2 a = anch[n]; ax = a.x; ay = a.y;
        size_t base = (size_t)(b * NN + n) * 5;
        px = pbx[base]; py = pbx[base + 1]; pth = pbx[base + 4];
#define LCOMP(d, i) { float sg = 1.f/(1.f+expf(-ps[base+i])); \
                      sg = fminf(fmaxf(sg, EPSF), 1.f); d = 0.5f*logf(sg+EPSF); }
        LCOMP(l0, 0) LCOMP(l1, 1) LCOMP(l2, 2) LCOMP(l3, 3) LCOMP(l4, 4)
#undef LCOMP
    }

    float bv = -1.f; int bgid = 0;
    float* amp = d_am + (size_t)b * GG * NN + n;

    for (int g = 0; g < GG; g++) {
        GTC q = s_gt[g];
        float dxa = ax - q.gx, dya = ay - q.gy;
        float lx = dxa * q.ct - dya * q.st;
        float ly = dxa * q.st + dya * q.ct;
        bool in = valid && (fabsf(lx) < q.w15) && (fabsf(ly) < q.h15);
        unsigned bal = __ballot_sync(0xffffffffu, in);
        if ((tid & 31) == 0 && bal) atomicAdd(&s_cnt[g], __popc(bal));
        float v = 0.f;
        if ((q.flags & 1) && bal) {
            if (in) {
                float dxp = px - q.gx, dyp = py - q.gy;
                float t = (dxp * dxp + dyp * dyp) * q.inv_s2;
                float x = expf(-t) + EPSF;               // ov + EPS
                float x2 = x * x; float x6 = x2 * x2 * x2;
                float wv = (pth - q.gth) + HPI_F;
                wv -= PI_F * floorf(wv * IPI_F);
                float wr = fabsf(wv - HPI_F);
                float c = (dxa * dxa + dya * dya) * q.inv_sc2;
                int lb = q.lbl;
                float lcl = lb == 0 ? l0 : (lb == 1 ? l1 : (lb == 2 ? l2 : (lb == 3 ? l3 : l4)));
                v = fmaxf(q.factor * x6 * expf(lcl - 1.5f * wr - c), 0.f);
            }
        }
        if (valid) amp[(size_t)g * NN] = v;
        if (v > bv) { bv = v; bgid = g; }   // ascending g -> first-max
    }
    __syncthreads();
    if (tid < GG) atomicAdd(&d_cnt[b * GG + tid], s_cnt[tid]);
    if (valid) {
        int idx = b * NN + n;
        d_best[idx] = ((unsigned long long)__float_as_uint(fmaxf(bv, 0.f)) << 32) |
                      (unsigned)(127 - bgid);
        d_norm[idx] = 0;
        d_pos[idx]  = 0;
    }
}

// ---------------------------------------------------------------------------
// B: block per (b,g). Load am row to smem, rare fallback, top-18 with
// cooperative winner-warp rescan, warp-0 epilogue.
// ---------------------------------------------------------------------------
__global__ __launch_bounds__(256) void topk_kernel(const float2* __restrict__ anch,
                                                   const float* __restrict__ ps,
                                                   const float* __restrict__ pbx) {
    int bg = blockIdx.x;
    int b  = bg >> 7;
    GTC q = d_gt[bg];
    if (!(q.flags & 1)) return;

    int tid = threadIdx.x, lane = tid & 31, wid = tid >> 5;

    __shared__ float              s_av[NN];        // 33.6 KB
    __shared__ unsigned long long s_rm[256];
    __shared__ unsigned long long s_red[2][8];
    __shared__ unsigned long long s_topk[MAXTK];
    __shared__ unsigned int       s_chosen[8];

    {
        float4*       av4 = (float4*)s_av;
        const float4* am4 = (const float4*)(d_am + (size_t)bg * NN);
        for (int i = tid; i < NN / 4; i += 256) av4[i] = am4[i];
    }
    s_rm[tid] = (tid >= 208) ? (1ull << 32) : 0ull;   // slot 32 invalid past n=8399
    __syncthreads();

    // -------- tiny/elongated fallback (rare) --------
    if (d_cnt[bg] == 0 && (q.flags & 2)) {
        for (int r = 0; r < 8; r++) {
            unsigned long long key = 0xFFFFFFFFFFFFFFFFull;
            for (int sl = 0; sl < NPT; sl++) {
                int n = sl * 256 + tid;
                if (n < NN) {
                    bool skip = false;
                    for (int qq = 0; qq < r; qq++)
                        if (s_chosen[qq] == (unsigned)n) skip = true;
                    if (!skip) {
                        float2 a = anch[n];
                        float dx = a.x - q.gx, dy = a.y - q.gy;
                        float d2 = dx * dx + dy * dy;
                        unsigned long long k =
                            ((unsigned long long)__float_as_uint(d2) << 32) | (unsigned)n;
                        if (k < key) key = k;
                    }
                }
            }
#pragma unroll
            for (int o = 16; o; o >>= 1) {
                unsigned long long t = __shfl_xor_sync(0xffffffffu, key, o);
                if (t < key) key = t;
            }
            if (lane == 0) s_red[0][wid] = key;
            __syncthreads();
            if (wid == 0) {
                unsigned long long v = (lane < 8) ? s_red[0][lane] : 0xFFFFFFFFFFFFFFFFull;
#pragma unroll
                for (int o = 4; o; o >>= 1) {
                    unsigned long long t = __shfl_xor_sync(0xffffffffu, v, o);
                    if (t < v) v = t;
                }
                if (lane == 0) s_chosen[r] = (unsigned)(v & 0xffffffffu);
            }
            __syncthreads();
            unsigned nw = s_chosen[r];
            if (r < q.fbk && (int)(nw & 255u) == tid) {
                int n = (int)nw;
                float2 a = anch[n];
                float dxa = a.x - q.gx, dya = a.y - q.gy;
                size_t base = (size_t)(b * NN + n) * 5;
                float dxp = pbx[base] - q.gx, dyp = pbx[base + 1] - q.gy;
                float t = (dxp * dxp + dyp * dyp) * q.inv_s2;
                float x = expf(-t) + EPSF;
                float x2 = x * x; float x6 = x2 * x2 * x2;
                float wv = (pbx[base + 4] - q.gth) + HPI_F;
                wv -= PI_F * floorf(wv * IPI_F);
                float wr = fabsf(wv - HPI_F);
                float c = (dxa * dxa + dya * dya) * q.inv_sc2;
                float sg = 1.f / (1.f + expf(-ps[base + q.lbl]));
                sg = fminf(fmaxf(sg, EPSF), 1.f);
                float lcl = 0.5f * logf(sg + EPSF);
                float v = fmaxf(q.factor * x6 * expf(lcl - 1.5f * wr - c), 0.f);
                s_av[n] = v;
                d_am[(size_t)bg * NN + n] = v;
                unsigned long long bk =
                    ((unsigned long long)__float_as_uint(v) << 32) |
                    (unsigned)(127 - (bg & 127));
                atomicMax((unsigned long long*)(d_best + b * NN + n), bk);
            }
            __syncthreads();
        }
    }

    // -------- top-18: column maxima, cooperative winner-warp rescan --------
    unsigned long long cur = 0ull;
    for (int sl = 0; sl < NPT; sl++) {
        int n = sl * 256 + tid;
        if (n < NN) {
            unsigned long long k =
                ((unsigned long long)__float_as_uint(s_av[n]) << 32) | (unsigned)(16384 - n);
            if (k > cur) cur = k;
        }
    }
    for (int r = 0; r < MAXTK; r++) {
        unsigned long long k = cur;
#pragma unroll
        for (int o = 16; o; o >>= 1) {
            unsigned long long t = __shfl_xor_sync(0xffffffffu, k, o);
            if (t > k) k = t;
        }
        if (lane == 0) s_red[r & 1][wid] = k;
        __syncthreads();
        unsigned long long best = s_red[r & 1][0];
#pragma unroll
        for (int i = 1; i < 8; i++) {
            unsigned long long t = s_red[r & 1][i];
            if (t > best) best = t;
        }
        if (tid == 0) s_topk[r] = best;
        unsigned nw = 16384u - (unsigned)(best & 0xffffffffu);
        int c = (int)(nw & 255u);
        if (wid == (c >> 5)) {                       // winner's warp rescans
            if (lane == (c & 31)) s_rm[c] |= (1ull << (nw >> 8));
            __syncwarp();
            unsigned long long m = s_rm[c];
            unsigned long long mk = 0ull;
            {
                int sl = lane;
                if (!((m >> sl) & 1ull)) {
                    int n2 = sl * 256 + c;
                    unsigned long long kk =
                        ((unsigned long long)__float_as_uint(s_av[n2]) << 32) |
                        (unsigned)(16384 - n2);
                    mk = kk;
                }
                if (lane == 0 && !((m >> 32) & 1ull)) {
                    int n2 = 32 * 256 + c;
                    unsigned long long kk =
                        ((unsigned long long)__float_as_uint(s_av[n2]) << 32) |
                        (unsigned)(16384 - n2);
                    if (kk > mk) mk = kk;
                }
            }
#pragma unroll
            for (int o = 16; o; o >>= 1) {
                unsigned long long t = __shfl_xor_sync(0xffffffffu, mk, o);
                if (t > mk) mk = t;
            }
            if (lane == (c & 31)) cur = mk;
        }
    }
    __syncthreads();

    // -------- epilogue (warp 0) --------
    if (wid == 0) {
        int j = lane;
        float val = 0.f; unsigned nj = 0; float ovj = 0.f;
        if (j < MAXTK) {
            unsigned long long k = s_topk[j];
            val = __uint_as_float((unsigned)(k >> 32));
            nj = 16384u - (unsigned)(k & 0xffffffffu);
            size_t base = (size_t)(b * NN + nj) * 5;
            float dx = pbx[base] - q.gx, dy = pbx[base + 1] - q.gy;
            float t = (dx * dx + dy * dy) * q.inv_s2;
            ovj = fminf(fmaxf(expf(-t), 0.f), 1.f);
        }
        float s = ovj;
#pragma unroll
        for (int o = 16; o; o >>= 1) s += __shfl_xor_sync(0xffffffffu, s, o);
        float dk = rintf(s);
        dk = fmaxf(dk, 1.f);
        dk = fminf(dk, (float)q.budget);
        int dyn = (int)dk;
        bool sel = (j < MAXTK) && (val > EPSF) && (j < dyn);
        unsigned bal = __ballot_sync(0xffffffffu, sel);
        if (bal) {
            int first = __ffs(bal) - 1;
            float maxalign = __shfl_sync(0xffffffffu, val, first);
            float mo = sel ? ovj : 0.f;
#pragma unroll
            for (int o = 16; o; o >>= 1) mo = fmaxf(mo, __shfl_xor_sync(0xffffffffu, mo, o));
            if (sel) {
                float nv = val * mo / (maxalign + EPSF);
                atomicMax(d_norm + b * NN + nj, __float_as_int(nv));
                d_pos[b * NN + nj] = 1;
            }
        }
    }
}

// ---------------------------------------------------------------------------
// D: trivial gather -> outputs [labels BN | bboxes 5BN | scores 5BN | pos BN]
// ---------------------------------------------------------------------------
__global__ __launch_bounds__(256) void out_kernel(const int* __restrict__ gl,
                                                  const float* __restrict__ gb,
                                                  float* __restrict__ out) {
    int idx = blockIdx.x * 256 + threadIdx.x;
    if (idx >= BN) return;
    int b = idx / NN;
    unsigned long long key = d_best[idx];
    int g = 127 - (int)(key & 0xffffffffull);
    bool pos = d_pos[idx] != 0;
    int lab = gl[b * GG + g];
    out[idx] = pos ? (float)lab : 5.f;
    const float* gp = gb + (size_t)(b * GG + g) * 5;
    float* ob = out + BN + (size_t)idx * 5;
    ob[0] = gp[0]; ob[1] = gp[1]; ob[2] = gp[2]; ob[3] = gp[3]; ob[4] = gp[4];
    float nv = __int_as_float(d_norm[idx]);
    float* os = out + (size_t)BN * 6 + (size_t)idx * 5;
#pragma unroll
    for (int c = 0; c < 5; c++) os[c] = (pos && c == lab) ? nv : 0.f;
    out[(size_t)BN * 11 + idx] = pos ? 1.f : 0.f;
}

// ---------------------------------------------------------------------------
extern "C" void kernel_launch(void* const* d_in, const int* in_sizes, int n_in,
                              void* d_out, int out_size) {
    const float* ps  = (const float*)d_in[0];
    const float* pbx = (const float*)d_in[1];
    const float* ap  = (const float*)d_in[2];
    const int*   gl  = (const int*)d_in[3];
    const float* gbx = (const float*)d_in[4];
    const float* mg  = (const float*)d_in[5];

    prep_gt<<<(BGT + 255) / 256, 256>>>(gl, gbx, mg);
    dim3 ga(NPT, BB);
    pair_kernel<<<ga, 256>>>((const float2*)ap, ps, pbx);
    topk_kernel<<<BGT, 256>>>((const float2*)ap, ps, pbx);
    out_kernel<<<(BN + 255) / 256, 256>>>(gl, gbx, (float*)d_out);
}

// round 4
// speedup vs baseline: 1.6544x; 1.2206x over previous
#include <cuda_runtime.h>
#include <math.h>

#define BB 16
#define NN 8400
#define GG 128
#define NCL 5
#define BN (BB*NN)      // 134400
#define BGT (BB*GG)     // 2048
#define NPT 33          // ceil(8400/256)
#define MAXTK 18
#define EPSF 1e-9f
#define HPI_F 1.57079632679489662f
#define PI_F  3.14159265358979323f
#define IPI_F 0.318309886183790672f

struct GTC {
    float gx, gy, ct, st;
    float w15, h15, inv_s2, inv_sc2;
    float factor, gth;
    int budget, fbk, flags, lbl;
    float pad0, pad1;
};

__device__ GTC                d_gt[BGT];
__device__ float              d_am[(size_t)BGT * NN];  // [b][g][n]
__device__ unsigned long long d_best[BN];              // (val<<32)|(127-g)
__device__ int                d_norm[BN];
__device__ unsigned char      d_pos[BN];
__device__ int                d_cnt[BGT];              // nonzero in-center flag

// ---------------------------------------------------------------------------
__global__ __launch_bounds__(256) void prep_gt(const int* __restrict__ gl,
                                               const float* __restrict__ gb,
                                               const float* __restrict__ mg) {
    int bg = blockIdx.x * 256 + threadIdx.x;
    if (bg >= BGT) return;
    const float* g = gb + (size_t)bg * 5;
    float gx = g[0], gy = g[1], w = g[2], h = g[3], th = g[4];
    float wc = fmaxf(w, EPSF), hc = fmaxf(h, EPSF);
    float area = wc * hc;
    float ar = fmaxf(wc / hc, hc / wc);
    float sev = fminf(fmaxf((0.01f - area) / (0.01f + EPSF), 0.f), 1.f);
    int te = (int)ceilf(sev * 4.f);
    int el = (ar >= 4.f) ? 1 : 0;
    GTC q;
    q.gx = gx; q.gy = gy;
    q.ct = cosf(-th); q.st = sinf(-th);
    q.w15 = w * 1.5f; q.h15 = h * 1.5f;
    float sc = sqrtf(w * h);
    float is = 1.f / (sc + 1e-6f);         q.inv_s2  = is * is;
    float isc = 1.f / (sc * 1.5f + 1e-6f); q.inv_sc2 = isc * isc;
    float strength = fminf(fmaxf((ar - 4.f) / (4.f + EPSF), 0.f), 1.f);
    q.factor = (1.f + sev * (4.f / 13.f)) * (1.f + 0.25f * strength);
    q.gth = th;
    q.budget = 13 + te + el;
    q.fbk = te + el + 3;
    int fl = (mg[bg] > 0.f) ? 1 : 0;
    if ((area < 0.01f) || (ar >= 4.f)) fl |= 2;
    q.flags = fl;
    q.lbl = gl[bg];
    q.pad0 = 0.f; q.pad1 = 0.f;
    d_gt[bg] = q;
    d_cnt[bg] = 0;
}

// ---------------------------------------------------------------------------
// A: block = (1024-anchor tile, b), 512 threads, 2 anchors/thread.
// ---------------------------------------------------------------------------
__global__ __launch_bounds__(512) void pair_kernel(const float4* __restrict__ anch4,
                                                   const float* __restrict__ ps,
                                                   const float* __restrict__ pbx) {
    int b   = blockIdx.y;
    int tid = threadIdx.x;
    int n0  = blockIdx.x * 1024 + tid * 2;

    __shared__ GTC           s_gt[GG];     // 8 KB
    __shared__ unsigned char s_any[GG];

    {
        const float4* src = (const float4*)(d_gt + b * GG);
        float4*       dst = (float4*)s_gt;
        for (int i = tid; i < GG * 4; i += 512) dst[i] = src[i];
        if (tid < GG) s_any[tid] = 0;
    }
    __syncthreads();

    bool valid = (n0 < NN);
    float ax0 = 0.f, ay0 = 0.f, ax1 = 0.f, ay1 = 0.f;
    float px0 = 0.f, py0 = 0.f, pt0 = 0.f, px1 = 0.f, py1 = 0.f, pt1 = 0.f;
    float l00 = 0.f, l01 = 0.f, l02 = 0.f, l03 = 0.f, l04 = 0.f;
    float l10 = 0.f, l11 = 0.f, l12 = 0.f, l13 = 0.f, l14 = 0.f;
    if (valid) {
        float4 a = anch4[n0 >> 1];
        ax0 = a.x; ay0 = a.y; ax1 = a.z; ay1 = a.w;
        size_t base = (size_t)(b * NN + n0) * 5;
        px0 = pbx[base];     py0 = pbx[base + 1]; pt0 = pbx[base + 4];
        px1 = pbx[base + 5]; py1 = pbx[base + 6]; pt1 = pbx[base + 9];
#define LC(d, i) { float sg = 1.f/(1.f+expf(-ps[base+(i)])); \
                   sg = fminf(fmaxf(sg, EPSF), 1.f); d = 0.5f*logf(sg+EPSF); }
        LC(l00,0) LC(l01,1) LC(l02,2) LC(l03,3) LC(l04,4)
        LC(l10,5) LC(l11,6) LC(l12,7) LC(l13,8) LC(l14,9)
#undef LC
    }

    float bv0 = 0.f, bv1 = 0.f;
    int   bg0 = 0,   bg1 = 0;
    float* amp = d_am + (size_t)b * GG * NN + n0;

    for (int g = 0; g < GG; g++) {
        GTC q = s_gt[g];
        if (!(q.flags & 1)) continue;          // masked: row never read, bv sees 0
        float dxa0 = ax0 - q.gx, dya0 = ay0 - q.gy;
        float dxa1 = ax1 - q.gx, dya1 = ay1 - q.gy;
        float lx0 = dxa0 * q.ct - dya0 * q.st, ly0 = dxa0 * q.st + dya0 * q.ct;
        float lx1 = dxa1 * q.ct - dya1 * q.st, ly1 = dxa1 * q.st + dya1 * q.ct;
        bool in0 = valid && (fabsf(lx0) < q.w15) && (fabsf(ly0) < q.h15);
        bool in1 = valid && (fabsf(lx1) < q.w15) && (fabsf(ly1) < q.h15);
        float vv0 = 0.f, vv1 = 0.f;
        if (__ballot_sync(0xffffffffu, in0 | in1)) {
            if ((tid & 31) == 0) s_any[g] = 1;
            int lb = q.lbl;
            if (in0) {
                float dxp = px0 - q.gx, dyp = py0 - q.gy;
                float t = (dxp * dxp + dyp * dyp) * q.inv_s2;
                float x = expf(-t) + EPSF;
                float x2 = x * x; float x6 = x2 * x2 * x2;
                float wv = (pt0 - q.gth) + HPI_F;
                wv -= PI_F * floorf(wv * IPI_F);
                float wr = fabsf(wv - HPI_F);
                float c = (dxa0 * dxa0 + dya0 * dya0) * q.inv_sc2;
                float lcl = lb == 0 ? l00 : (lb == 1 ? l01 : (lb == 2 ? l02 : (lb == 3 ? l03 : l04)));
                vv0 = fmaxf(q.factor * x6 * expf(lcl - 1.5f * wr - c), 0.f);
            }
            if (in1) {
                float dxp = px1 - q.gx, dyp = py1 - q.gy;
                float t = (dxp * dxp + dyp * dyp) * q.inv_s2;
                float x = expf(-t) + EPSF;
                float x2 = x * x; float x6 = x2 * x2 * x2;
                float wv = (pt1 - q.gth) + HPI_F;
                wv -= PI_F * floorf(wv * IPI_F);
                float wr = fabsf(wv - HPI_F);
                float c = (dxa1 * dxa1 + dya1 * dya1) * q.inv_sc2;
                float lcl = lb == 0 ? l10 : (lb == 1 ? l11 : (lb == 2 ? l12 : (lb == 3 ? l13 : l14)));
                vv1 = fmaxf(q.factor * x6 * expf(lcl - 1.5f * wr - c), 0.f);
            }
        }
        if (valid) *(float2*)(amp + (size_t)g * NN) = make_float2(vv0, vv1);
        if (vv0 > bv0) { bv0 = vv0; bg0 = g; }
        if (vv1 > bv1) { bv1 = vv1; bg1 = g; }
    }
    __syncthreads();
    if (tid < GG && s_any[tid]) atomicOr(&d_cnt[b * GG + tid], 1);
    if (valid) {
        int idx = b * NN + n0;
        d_best[idx] = ((unsigned long long)__float_as_uint(bv0) << 32) | (unsigned)(127 - bg0);
        d_best[idx + 1] = ((unsigned long long)__float_as_uint(bv1) << 32) | (unsigned)(127 - bg1);
        d_norm[idx] = 0; d_norm[idx + 1] = 0;
        d_pos[idx] = 0;  d_pos[idx + 1] = 0;
    }
}

// ---------------------------------------------------------------------------
// B: block per (b,g). am row -> smem, rare fallback, REDUX-based top-18.
// ---------------------------------------------------------------------------
__global__ __launch_bounds__(256) void topk_kernel(const float2* __restrict__ anch,
                                                   const float* __restrict__ ps,
                                                   const float* __restrict__ pbx) {
    int bg = blockIdx.x;
    int b  = bg >> 7;
    GTC q = d_gt[bg];
    if (!(q.flags & 1)) return;

    int tid = threadIdx.x, lane = tid & 31, wid = tid >> 5;

    __shared__ float              s_av[NN];        // 33.6 KB
    __shared__ unsigned long long s_rm[256];
    __shared__ unsigned long long s_w[2][8];
    __shared__ unsigned long long s_topk[MAXTK];
    __shared__ unsigned int       s_chosen[8];

    {
        float4*       av4 = (float4*)s_av;
        const float4* am4 = (const float4*)(d_am + (size_t)bg * NN);
        for (int i = tid; i < NN / 4; i += 256) av4[i] = am4[i];
    }
    s_rm[tid] = (tid >= 208) ? (1ull << 32) : 0ull;
    __syncthreads();

    // -------- tiny/elongated fallback (rare) --------
    if (d_cnt[bg] == 0 && (q.flags & 2)) {
        for (int r = 0; r < 8; r++) {
            unsigned long long key = 0xFFFFFFFFFFFFFFFFull;
            for (int sl = 0; sl < NPT; sl++) {
                int n = sl * 256 + tid;
                if (n < NN) {
                    bool skip = false;
                    for (int qq = 0; qq < r; qq++)
                        if (s_chosen[qq] == (unsigned)n) skip = true;
                    if (!skip) {
                        float2 a = anch[n];
                        float dx = a.x - q.gx, dy = a.y - q.gy;
                        float d2 = dx * dx + dy * dy;
                        unsigned long long k =
                            ((unsigned long long)__float_as_uint(d2) << 32) | (unsigned)n;
                        if (k < key) key = k;
                    }
                }
            }
#pragma unroll
            for (int o = 16; o; o >>= 1) {
                unsigned long long t = __shfl_xor_sync(0xffffffffu, key, o);
                if (t < key) key = t;
            }
            if (lane == 0) s_w[0][wid] = key;
            __syncthreads();
            if (wid == 0) {
                unsigned long long v = (lane < 8) ? s_w[0][lane] : 0xFFFFFFFFFFFFFFFFull;
#pragma unroll
                for (int o = 4; o; o >>= 1) {
                    unsigned long long t = __shfl_xor_sync(0xffffffffu, v, o);
                    if (t < v) v = t;
                }
                if (lane == 0) s_chosen[r] = (unsigned)(v & 0xffffffffu);
            }
            __syncthreads();
            unsigned nw = s_chosen[r];
            if (r < q.fbk && (int)(nw & 255u) == tid) {
                int n = (int)nw;
                float2 a = anch[n];
                float dxa = a.x - q.gx, dya = a.y - q.gy;
                size_t base = (size_t)(b * NN + n) * 5;
                float dxp = pbx[base] - q.gx, dyp = pbx[base + 1] - q.gy;
                float t = (dxp * dxp + dyp * dyp) * q.inv_s2;
                float x = expf(-t) + EPSF;
                float x2 = x * x; float x6 = x2 * x2 * x2;
                float wv = (pbx[base + 4] - q.gth) + HPI_F;
                wv -= PI_F * floorf(wv * IPI_F);
                float wr = fabsf(wv - HPI_F);
                float c = (dxa * dxa + dya * dya) * q.inv_sc2;
                float sg = 1.f / (1.f + expf(-ps[base + q.lbl]));
                sg = fminf(fmaxf(sg, EPSF), 1.f);
                float lcl = 0.5f * logf(sg + EPSF);
                float v = fmaxf(q.factor * x6 * expf(lcl - 1.5f * wr - c), 0.f);
                s_av[n] = v;
                d_am[(size_t)bg * NN + n] = v;
                unsigned long long bk =
                    ((unsigned long long)__float_as_uint(v) << 32) |
                    (unsigned)(127 - (bg & 127));
                atomicMax((unsigned long long*)(d_best + b * NN + n), bk);
            }
            __syncthreads();
        }
    }

    // -------- column maxima --------
    float cv = -1.f; int cn = 0;
    for (int sl = 0; sl < NPT; sl++) {
        int n = sl * 256 + tid;
        if (n < NN) {
            float v = s_av[n];
            if (v > cv) { cv = v; cn = n; }   // keep-first -> min n per column
        }
    }

    // -------- 18 extraction rounds (REDUX + 1 barrier) --------
    for (int r = 0; r < MAXTK; r++) {
        unsigned vb   = __float_as_uint(cv);
        unsigned wmax = __reduce_max_sync(0xffffffffu, vb);
        unsigned nk   = __reduce_max_sync(0xffffffffu,
                                          (vb == wmax) ? (unsigned)(16384 - cn) : 0u);
        if (lane == 0)
            s_w[r & 1][wid] = ((unsigned long long)wmax << 32) | nk;
        __syncthreads();
        unsigned long long best = s_w[r & 1][0];
#pragma unroll
        for (int i = 1; i < 8; i++) {
            unsigned long long t = s_w[r & 1][i];
            if (t > best) best = t;
        }
        if (tid == 0) s_topk[r] = best;
        int bn = 16384 - (int)(best & 0xffffffffull);
        int c  = bn & 255;
        if (wid == (c >> 5)) {                        // owner warp rescans column c
            if (lane == (c & 31)) s_rm[c] |= (1ull << (bn >> 8));
            __syncwarp();
            unsigned long long m = s_rm[c];
            unsigned vb2 = 0u; unsigned nk2raw = 0u;
            {
                int sl = lane;
                if (!((m >> sl) & 1ull)) {
                    int n2 = sl * 256 + c;
                    vb2 = __float_as_uint(s_av[n2]);
                    nk2raw = (unsigned)(16384 - n2);
                }
                if (lane == 0 && !((m >> 32) & 1ull)) {
                    int n2 = 32 * 256 + c;
                    unsigned v2 = __float_as_uint(s_av[n2]);
                    if (v2 > vb2) { vb2 = v2; nk2raw = (unsigned)(16384 - n2); }
                    else if (v2 == vb2 && (unsigned)(16384 - n2) > nk2raw)
                        nk2raw = (unsigned)(16384 - n2);
                }
            }
            unsigned wm2 = __reduce_max_sync(0xffffffffu, vb2);
            unsigned nn2 = __reduce_max_sync(0xffffffffu, (vb2 == wm2) ? nk2raw : 0u);
            if (lane == (c & 31)) { cv = __uint_as_float(wm2); cn = 16384 - (int)nn2; }
        }
    }
    __syncthreads();

    // -------- epilogue (warp 0) --------
    if (wid == 0) {
        int j = lane;
        float val = 0.f; unsigned nj = 0; float ovj = 0.f;
        if (j < MAXTK) {
            unsigned long long k = s_topk[j];
            val = __uint_as_float((unsigned)(k >> 32));
            nj = 16384u - (unsigned)(k & 0xffffffffull);
            size_t base = (size_t)(b * NN + nj) * 5;
            float dx = pbx[base] - q.gx, dy = pbx[base + 1] - q.gy;
            float t = (dx * dx + dy * dy) * q.inv_s2;
            ovj = fminf(fmaxf(expf(-t), 0.f), 1.f);
        }
        float s = ovj;
#pragma unroll
        for (int o = 16; o; o >>= 1) s += __shfl_xor_sync(0xffffffffu, s, o);
        float dk = rintf(s);
        dk = fmaxf(dk, 1.f);
        dk = fminf(dk, (float)q.budget);
        int dyn = (int)dk;
        bool sel = (j < MAXTK) && (val > EPSF) && (j < dyn);
        unsigned bal = __ballot_sync(0xffffffffu, sel);
        if (bal) {
            int first = __ffs(bal) - 1;
            float maxalign = __shfl_sync(0xffffffffu, val, first);
            float mo = sel ? ovj : 0.f;
#pragma unroll
            for (int o = 16; o; o >>= 1) mo = fmaxf(mo, __shfl_xor_sync(0xffffffffu, mo, o));
            if (sel) {
                float nv = val * mo / (maxalign + EPSF);
                atomicMax(d_norm + b * NN + nj, __float_as_int(nv));
                d_pos[b * NN + nj] = 1;
            }
        }
    }
}

// ---------------------------------------------------------------------------
__global__ __launch_bounds__(256) void out_kernel(const int* __restrict__ gl,
                                                  const float* __restrict__ gb,
                                                  float* __restrict__ out) {
    int idx = blockIdx.x * 256 + threadIdx.x;
    if (idx >= BN) return;
    int b = idx / NN;
    unsigned long long key = d_best[idx];
    int g = 127 - (int)(key & 0xffffffffull);
    bool pos = d_pos[idx] != 0;
    int lab = gl[b * GG + g];
    out[idx] = pos ? (float)lab : 5.f;
    const float* gp = gb + (size_t)(b * GG + g) * 5;
    float* ob = out + BN + (size_t)idx * 5;
    ob[0] = gp[0]; ob[1] = gp[1]; ob[2] = gp[2]; ob[3] = gp[3]; ob[4] = gp[4];
    float nv = __int_as_float(d_norm[idx]);
    float* os = out + (size_t)BN * 6 + (size_t)idx * 5;
#pragma unroll
    for (int c = 0; c < 5; c++) os[c] = (pos && c == lab) ? nv : 0.f;
    out[(size_t)BN * 11 + idx] = pos ? 1.f : 0.f;
}

// ---------------------------------------------------------------------------
extern "C" void kernel_launch(void* const* d_in, const int* in_sizes, int n_in,
                              void* d_out, int out_size) {
    const float* ps  = (const float*)d_in[0];
    const float* pbx = (const float*)d_in[1];
    const float* ap  = (const float*)d_in[2];
    const int*   gl  = (const int*)d_in[3];
    const float* gbx = (const float*)d_in[4];
    const float* mg  = (const float*)d_in[5];

    prep_gt<<<(BGT + 255) / 256, 256>>>(gl, gbx, mg);
    dim3 ga((NN + 1023) / 1024, BB);
    pair_kernel<<<ga, 512>>>((const float4*)ap, ps, pbx);
    topk_kernel<<<BGT, 256>>>((const float2*)ap, ps, pbx);
    out_kernel<<<(BN + 255) / 256, 256>>>(gl, gbx, (float*)d_out);
}

// round 5
// speedup vs baseline: 1.8533x; 1.1202x over previous
#include <cuda_runtime.h>
#include <math.h>

#define BB 16
#define NN 8400
#define GG 128
#define NCL 5
#define BN (BB*NN)      // 134400
#define BGT (BB*GG)     // 2048
#define NQ4 (NN/4)      // 2100 float4s per row
#define MAXTK 18
#define EPSF 1e-9f
#define HPI_F 1.57079632679489662f
#define PI_F  3.14159265358979323f
#define IPI_F 0.318309886183790672f

typedef unsigned long long u64;

struct GTC {
    float gx, gy, ct, st;
    float w15, h15, inv_s2, inv_sc2;
    float factor, gth;
    int budget, fbk, flags, lbl;
    float pad0, pad1;
};

__device__ GTC           d_gt[BGT];
__device__ float         d_am[(size_t)BGT * NN];  // [b][g][n]
__device__ u64           d_best[BN];              // (val<<32)|(127-g)
__device__ int           d_norm[BN];
__device__ unsigned char d_pos[BN];
__device__ int           d_cnt[BGT];              // nonzero in-center flag

// ---------------------------------------------------------------------------
__global__ __launch_bounds__(256) void prep_gt(const int* __restrict__ gl,
                                               const float* __restrict__ gb,
                                               const float* __restrict__ mg) {
    int bg = blockIdx.x * 256 + threadIdx.x;
    if (bg >= BGT) return;
    const float* g = gb + (size_t)bg * 5;
    float gx = g[0], gy = g[1], w = g[2], h = g[3], th = g[4];
    float wc = fmaxf(w, EPSF), hc = fmaxf(h, EPSF);
    float area = wc * hc;
    float ar = fmaxf(wc / hc, hc / wc);
    float sev = fminf(fmaxf((0.01f - area) / (0.01f + EPSF), 0.f), 1.f);
    int te = (int)ceilf(sev * 4.f);
    int el = (ar >= 4.f) ? 1 : 0;
    GTC q;
    q.gx = gx; q.gy = gy;
    q.ct = cosf(-th); q.st = sinf(-th);
    q.w15 = w * 1.5f; q.h15 = h * 1.5f;
    float sc = sqrtf(w * h);
    float is = 1.f / (sc + 1e-6f);         q.inv_s2  = is * is;
    float isc = 1.f / (sc * 1.5f + 1e-6f); q.inv_sc2 = isc * isc;
    float strength = fminf(fmaxf((ar - 4.f) / (4.f + EPSF), 0.f), 1.f);
    q.factor = (1.f + sev * (4.f / 13.f)) * (1.f + 0.25f * strength);
    q.gth = th;
    q.budget = 13 + te + el;
    q.fbk = te + el + 3;
    int fl = (mg[bg] > 0.f) ? 1 : 0;
    if ((area < 0.01f) || (ar >= 4.f)) fl |= 2;
    q.flags = fl;
    q.lbl = gl[bg];
    q.pad0 = 0.f; q.pad1 = 0.f;
    d_gt[bg] = q;
    d_cnt[bg] = 0;
}

// ---------------------------------------------------------------------------
// A: block = (1024-anchor tile, b), 512 threads, 2 anchors/thread, fast math.
// ---------------------------------------------------------------------------
__global__ __launch_bounds__(512) void pair_kernel(const float4* __restrict__ anch4,
                                                   const float* __restrict__ ps,
                                                   const float* __restrict__ pbx) {
    int b   = blockIdx.y;
    int tid = threadIdx.x;
    int n0  = blockIdx.x * 1024 + tid * 2;

    __shared__ GTC           s_gt[GG];     // 8 KB
    __shared__ unsigned char s_any[GG];

    {
        const float4* src = (const float4*)(d_gt + b * GG);
        float4*       dst = (float4*)s_gt;
        for (int i = tid; i < GG * 4; i += 512) dst[i] = src[i];
        if (tid < GG) s_any[tid] = 0;
    }
    __syncthreads();

    bool valid = (n0 < NN);
    float ax0 = 0.f, ay0 = 0.f, ax1 = 0.f, ay1 = 0.f;
    float px0 = 0.f, py0 = 0.f, pt0 = 0.f, px1 = 0.f, py1 = 0.f, pt1 = 0.f;
    float l00 = 0.f, l01 = 0.f, l02 = 0.f, l03 = 0.f, l04 = 0.f;
    float l10 = 0.f, l11 = 0.f, l12 = 0.f, l13 = 0.f, l14 = 0.f;
    if (valid) {
        float4 a = anch4[n0 >> 1];
        ax0 = a.x; ay0 = a.y; ax1 = a.z; ay1 = a.w;
        size_t base = (size_t)(b * NN + n0) * 5;
        px0 = pbx[base];     py0 = pbx[base + 1]; pt0 = pbx[base + 4];
        px1 = pbx[base + 5]; py1 = pbx[base + 6]; pt1 = pbx[base + 9];
#define LC(d, i) { float sg = 1.f/(1.f+__expf(-ps[base+(i)])); \
                   sg = fminf(fmaxf(sg, EPSF), 1.f); d = 0.5f*__logf(sg+EPSF); }
        LC(l00,0) LC(l01,1) LC(l02,2) LC(l03,3) LC(l04,4)
        LC(l10,5) LC(l11,6) LC(l12,7) LC(l13,8) LC(l14,9)
#undef LC
    }

    float bv0 = 0.f, bv1 = 0.f;
    int   bg0 = 0,   bg1 = 0;
    float* amp = d_am + (size_t)b * GG * NN + n0;

    for (int g = 0; g < GG; g++) {
        GTC q = s_gt[g];
        if (!(q.flags & 1)) continue;
        float dxa0 = ax0 - q.gx, dya0 = ay0 - q.gy;
        float dxa1 = ax1 - q.gx, dya1 = ay1 - q.gy;
        float lx0 = dxa0 * q.ct - dya0 * q.st, ly0 = dxa0 * q.st + dya0 * q.ct;
        float lx1 = dxa1 * q.ct - dya1 * q.st, ly1 = dxa1 * q.st + dya1 * q.ct;
        bool in0 = valid && (fabsf(lx0) < q.w15) && (fabsf(ly0) < q.h15);
        bool in1 = valid && (fabsf(lx1) < q.w15) && (fabsf(ly1) < q.h15);
        float vv0 = 0.f, vv1 = 0.f;
        if (__ballot_sync(0xffffffffu, in0 | in1)) {
            if ((tid & 31) == 0) s_any[g] = 1;
            int lb = q.lbl;
            if (in0) {
                float dxp = px0 - q.gx, dyp = py0 - q.gy;
                float t = (dxp * dxp + dyp * dyp) * q.inv_s2;
                float x = __expf(-t) + EPSF;
                float x2 = x * x; float x6 = x2 * x2 * x2;
                float wv = (pt0 - q.gth) + HPI_F;
                wv -= PI_F * floorf(wv * IPI_F);
                float wr = fabsf(wv - HPI_F);
                float c = (dxa0 * dxa0 + dya0 * dya0) * q.inv_sc2;
                float lcl = lb == 0 ? l00 : (lb == 1 ? l01 : (lb == 2 ? l02 : (lb == 3 ? l03 : l04)));
                vv0 = fmaxf(q.factor * x6 * __expf(lcl - 1.5f * wr - c), 0.f);
            }
            if (in1) {
                float dxp = px1 - q.gx, dyp = py1 - q.gy;
                float t = (dxp * dxp + dyp * dyp) * q.inv_s2;
                float x = __expf(-t) + EPSF;
                float x2 = x * x; float x6 = x2 * x2 * x2;
                float wv = (pt1 - q.gth) + HPI_F;
                wv -= PI_F * floorf(wv * IPI_F);
                float wr = fabsf(wv - HPI_F);
                float c = (dxa1 * dxa1 + dya1 * dya1) * q.inv_sc2;
                float lcl = lb == 0 ? l10 : (lb == 1 ? l11 : (lb == 2 ? l12 : (lb == 3 ? l13 : l14)));
                vv1 = fmaxf(q.factor * x6 * __expf(lcl - 1.5f * wr - c), 0.f);
            }
        }
        if (valid) *(float2*)(amp + (size_t)g * NN) = make_float2(vv0, vv1);
        if (vv0 > bv0) { bv0 = vv0; bg0 = g; }
        if (vv1 > bv1) { bv1 = vv1; bg1 = g; }
    }
    __syncthreads();
    if (tid < GG && s_any[tid]) atomicOr(&d_cnt[b * GG + tid], 1);
    if (valid) {
        int idx = b * NN + n0;
        d_best[idx]     = ((u64)__float_as_uint(bv0) << 32) | (unsigned)(127 - bg0);
        d_best[idx + 1] = ((u64)__float_as_uint(bv1) << 32) | (unsigned)(127 - bg1);
        d_norm[idx] = 0; d_norm[idx + 1] = 0;
        d_pos[idx] = 0;  d_pos[idx + 1] = 0;
    }
}

// ---------------------------------------------------------------------------
// B: block per (b,g). Copy row + column maxima in one pass, then warp-0-only
// 18-round extraction with zero block barriers. Column c = float4 lane layout:
// thread's values are i = c + k*256 (k = 0..8), n = 4i + j.
// ---------------------------------------------------------------------------
__global__ __launch_bounds__(256) void topk_kernel(const float2* __restrict__ anch,
                                                   const float* __restrict__ ps,
                                                   const float* __restrict__ pbx) {
    int bg = blockIdx.x;
    int b  = bg >> 7;
    GTC q = d_gt[bg];
    if (!(q.flags & 1)) return;

    int tid = threadIdx.x, lane = tid & 31, wid = tid >> 5;

    __shared__ float    s_av[NN];          // 33.6 KB
    __shared__ u64      s_cmax[256];
    __shared__ u64      s_rm[256];
    __shared__ u64      s_red[8];
    __shared__ unsigned s_chosen[8];

    const float4* am4 = (const float4*)(d_am + (size_t)bg * NN);
    float4*       av4 = (float4*)s_av;
    bool fb = (d_cnt[bg] == 0) && (q.flags & 2);

    u64 cm = 0;
    for (int i = tid; i < NQ4; i += 256) {
        float4 v = am4[i];
        av4[i] = v;
        float m4 = fmaxf(fmaxf(v.x, v.y), fmaxf(v.z, v.w));
        int j = (v.x == m4) ? 0 : ((v.y == m4) ? 1 : ((v.z == m4) ? 2 : 3));
        u64 key = ((u64)__float_as_uint(m4) << 32) | (unsigned)(16384 - (4 * i + j));
        if (key > cm) cm = key;
    }
    s_rm[tid] = 0;

    // -------- tiny/elongated fallback (rare) --------
    if (fb) {
        __syncthreads();
        for (int r = 0; r < 8; r++) {
            u64 key = 0xFFFFFFFFFFFFFFFFull;
            for (int n = tid; n < NN; n += 256) {
                bool skip = false;
                for (int qq = 0; qq < r; qq++)
                    if (s_chosen[qq] == (unsigned)n) skip = true;
                if (!skip) {
                    float2 a = anch[n];
                    float dx = a.x - q.gx, dy = a.y - q.gy;
                    float d2 = dx * dx + dy * dy;
                    u64 k = ((u64)__float_as_uint(d2) << 32) | (unsigned)n;
                    if (k < key) key = k;
                }
            }
#pragma unroll
            for (int o = 16; o; o >>= 1) {
                u64 t = __shfl_xor_sync(0xffffffffu, key, o);
                if (t < key) key = t;
            }
            if (lane == 0) s_red[wid] = key;
            __syncthreads();
            if (wid == 0) {
                u64 v = (lane < 8) ? s_red[lane] : 0xFFFFFFFFFFFFFFFFull;
#pragma unroll
                for (int o = 4; o; o >>= 1) {
                    u64 t = __shfl_xor_sync(0xffffffffu, v, o);
                    if (t < v) v = t;
                }
                if (lane == 0) s_chosen[r] = (unsigned)(v & 0xffffffffu);
            }
            __syncthreads();
            unsigned nw = s_chosen[r];
            if (r < q.fbk && (int)(nw & 255u) == tid) {
                int n = (int)nw;
                float2 a = anch[n];
                float dxa = a.x - q.gx, dya = a.y - q.gy;
                size_t base = (size_t)(b * NN + n) * 5;
                float dxp = pbx[base] - q.gx, dyp = pbx[base + 1] - q.gy;
                float t = (dxp * dxp + dyp * dyp) * q.inv_s2;
                float x = __expf(-t) + EPSF;
                float x2 = x * x; float x6 = x2 * x2 * x2;
                float wv = (pbx[base + 4] - q.gth) + HPI_F;
                wv -= PI_F * floorf(wv * IPI_F);
                float wr = fabsf(wv - HPI_F);
                float c = (dxa * dxa + dya * dya) * q.inv_sc2;
                float sg = 1.f / (1.f + __expf(-ps[base + q.lbl]));
                sg = fminf(fmaxf(sg, EPSF), 1.f);
                float lcl = 0.5f * __logf(sg + EPSF);
                float v = fmaxf(q.factor * x6 * __expf(lcl - 1.5f * wr - c), 0.f);
                s_av[n] = v;
                u64 bk = ((u64)__float_as_uint(v) << 32) | (unsigned)(127 - (bg & 127));
                atomicMax((u64*)(d_best + b * NN + n), bk);
            }
            __syncthreads();
        }
        // recompute column maxima after patches
        cm = 0;
        for (int i = tid; i < NQ4; i += 256) {
            float4 v = av4[i];
            float m4 = fmaxf(fmaxf(v.x, v.y), fmaxf(v.z, v.w));
            int j = (v.x == m4) ? 0 : ((v.y == m4) ? 1 : ((v.z == m4) ? 2 : 3));
            u64 key = ((u64)__float_as_uint(m4) << 32) | (unsigned)(16384 - (4 * i + j));
            if (key > cm) cm = key;
        }
    }

    s_cmax[tid] = cm;
    __syncthreads();
    if (wid != 0) return;

    // -------- warp-0-only 18-round extraction (no block barriers) --------
    u64 myk[8];
#pragma unroll
    for (int j2 = 0; j2 < 8; j2++) myk[j2] = s_cmax[lane * 8 + j2];
    u64 topkey = 0;

    for (int r = 0; r < MAXTK; r++) {
        u64 m = myk[0];
#pragma unroll
        for (int j2 = 1; j2 < 8; j2++) if (myk[j2] > m) m = myk[j2];
        unsigned hi = (unsigned)(m >> 32);
        unsigned hmax = __reduce_max_sync(0xffffffffu, hi);
        unsigned lo = (hi == hmax) ? (unsigned)m : 0u;
        unsigned lmax = __reduce_max_sync(0xffffffffu, lo);
        if (lane == r) topkey = ((u64)hmax << 32) | lmax;

        int bn = 16384 - (int)lmax;      // winner anchor index
        int bi = bn >> 2;
        int c  = bi & 255;               // owner column
        int mi = ((bi >> 8) << 2) | (bn & 3);
        if (lane == 0) s_rm[c] |= (1ull << mi);
        __syncwarp();
        u64 rmm = s_rm[c];
        int nv = (c < (NQ4 & 255)) ? 36 : 32;   // NQ4=2100 -> columns <52 have 9 float4s
        u64 nk = 0;
        {
            int mm = lane;
            if (!((rmm >> mm) & 1ull)) {
                int n2 = 4 * (c + (mm >> 2) * 256) + (mm & 3);
                nk = ((u64)__float_as_uint(s_av[n2]) << 32) | (unsigned)(16384 - n2);
            }
            if (nv == 36 && lane < 4) {
                int mm2 = 32 + lane;
                if (!((rmm >> mm2) & 1ull)) {
                    int n2 = 4 * (c + (mm2 >> 2) * 256) + (mm2 & 3);
                    u64 k2 = ((u64)__float_as_uint(s_av[n2]) << 32) | (unsigned)(16384 - n2);
                    if (k2 > nk) nk = k2;
                }
            }
        }
        unsigned h2 = (unsigned)(nk >> 32);
        unsigned hm2 = __reduce_max_sync(0xffffffffu, h2);
        unsigned lo2 = (h2 == hm2) ? (unsigned)nk : 0u;
        unsigned lm2 = __reduce_max_sync(0xffffffffu, lo2);
        u64 newmax = ((u64)hm2 << 32) | lm2;
        if (lane == (c >> 3)) {
            switch (c & 7) {
                case 0: myk[0] = newmax; break;
                case 1: myk[1] = newmax; break;
                case 2: myk[2] = newmax; break;
                case 3: myk[3] = newmax; break;
                case 4: myk[4] = newmax; break;
                case 5: myk[5] = newmax; break;
                case 6: myk[6] = newmax; break;
                case 7: myk[7] = newmax; break;
            }
        }
    }

    // -------- epilogue (warp 0) --------
    {
        float val = 0.f; unsigned nj = 0; float ovj = 0.f;
        if (lane < MAXTK) {
            val = __uint_as_float((unsigned)(topkey >> 32));
            nj = 16384u - (unsigned)(topkey & 0xffffffffull);
            size_t base = (size_t)(b * NN + nj) * 5;
            float dx = pbx[base] - q.gx, dy = pbx[base + 1] - q.gy;
            float t = (dx * dx + dy * dy) * q.inv_s2;
            ovj = fminf(fmaxf(__expf(-t), 0.f), 1.f);
        }
        float s = ovj;
#pragma unroll
        for (int o = 16; o; o >>= 1) s += __shfl_xor_sync(0xffffffffu, s, o);
        float dk = rintf(s);
        dk = fmaxf(dk, 1.f);
        dk = fminf(dk, (float)q.budget);
        int dyn = (int)dk;
        bool sel = (lane < MAXTK) && (val > EPSF) && (lane < dyn);
        unsigned bal = __ballot_sync(0xffffffffu, sel);
        if (bal) {
            int first = __ffs(bal) - 1;
            float maxalign = __shfl_sync(0xffffffffu, val, first);
            float mo = sel ? ovj : 0.f;
#pragma unroll
            for (int o = 16; o; o >>= 1) mo = fmaxf(mo, __shfl_xor_sync(0xffffffffu, mo, o));
            if (sel) {
                float nv2 = val * mo / (maxalign + EPSF);
                atomicMax(d_norm + b * NN + nj, __float_as_int(nv2));
                d_pos[b * NN + nj] = 1;
            }
        }
    }
}

// ---------------------------------------------------------------------------
__global__ __launch_bounds__(256) void out_kernel(const int* __restrict__ gl,
                                                  const float* __restrict__ gb,
                                                  float* __restrict__ out) {
    int idx = blockIdx.x * 256 + threadIdx.x;
    if (idx >= BN) return;
    int b = idx / NN;
    u64 key = d_best[idx];
    int g = 127 - (int)(key & 0xffffffffull);
    bool pos = d_pos[idx] != 0;
    int lab = gl[b * GG + g];
    out[idx] = pos ? (float)lab : 5.f;
    const float* gp = gb + (size_t)(b * GG + g) * 5;
    float* ob = out + BN + (size_t)idx * 5;
    ob[0] = gp[0]; ob[1] = gp[1]; ob[2] = gp[2]; ob[3] = gp[3]; ob[4] = gp[4];
    float nv = __int_as_float(d_norm[idx]);
    float* os = out + (size_t)BN * 6 + (size_t)idx * 5;
#pragma unroll
    for (int c = 0; c < 5; c++) os[c] = (pos && c == lab) ? nv : 0.f;
    out[(size_t)BN * 11 + idx] = pos ? 1.f : 0.f;
}

// ---------------------------------------------------------------------------
extern "C" void kernel_launch(void* const* d_in, const int* in_sizes, int n_in,
                              void* d_out, int out_size) {
    const float* ps  = (const float*)d_in[0];
    const float* pbx = (const float*)d_in[1];
    const float* ap  = (const float*)d_in[2];
    const int*   gl  = (const int*)d_in[3];
    const float* gbx = (const float*)d_in[4];
    const float* mg  = (const float*)d_in[5];

    prep_gt<<<(BGT + 255) / 256, 256>>>(gl, gbx, mg);
    dim3 ga((NN + 1023) / 1024, BB);
    pair_kernel<<<ga, 512>>>((const float4*)ap, ps, pbx);
    topk_kernel<<<BGT, 256>>>((const float2*)ap, ps, pbx);
    out_kernel<<<(BN + 255) / 256, 256>>>(gl, gbx, (float*)d_out);
}